// round 1
// baseline (speedup 1.0000x reference)
#include <cuda_runtime.h>
#include <cuda_bf16.h>

#define BB 16
#define NN 32768
#define CC 64
#define RR 32
#define R3 (RR*RR*RR)
#define EPSF 1e-6f

// Scratch (device globals — no allocation allowed)
__device__ float g_sums[(size_t)BB * R3 * CC];   // [b][voxel][c]
__device__ int   g_cnt[BB * R3];                  // [b][voxel]
__device__ float g_mean[BB][3];
__device__ float g_denom[BB];
__device__ int   g_idx[BB * NN];                  // voxel index per point

// ---------------------------------------------------------------------------
// Zero the accumulators (needed every launch; graph replays reuse scratch)
// ---------------------------------------------------------------------------
__global__ void k_zero() {
    size_t stride = (size_t)gridDim.x * blockDim.x;
    size_t i = (size_t)blockIdx.x * blockDim.x + threadIdx.x;
    float4* s4 = reinterpret_cast<float4*>(g_sums);
    const size_t tot4 = (size_t)BB * R3 * CC / 4;
    for (size_t j = i; j < tot4; j += stride)
        s4[j] = make_float4(0.f, 0.f, 0.f, 0.f);
    const size_t totc = (size_t)BB * R3;
    for (size_t j = i; j < totc; j += stride)
        g_cnt[j] = 0;
}

// ---------------------------------------------------------------------------
// Per-batch mean of coords (one block per batch)
// ---------------------------------------------------------------------------
__global__ void k_mean(const float* __restrict__ coords) {
    const int b = blockIdx.x;
    const float* cb = coords + (size_t)b * NN * 3;
    float sx = 0.f, sy = 0.f, sz = 0.f;
    for (int n = threadIdx.x; n < NN; n += blockDim.x) {
        sx += cb[n * 3 + 0];
        sy += cb[n * 3 + 1];
        sz += cb[n * 3 + 2];
    }
    __shared__ float sh[3][32];
    #pragma unroll
    for (int off = 16; off; off >>= 1) {
        sx += __shfl_down_sync(0xffffffffu, sx, off);
        sy += __shfl_down_sync(0xffffffffu, sy, off);
        sz += __shfl_down_sync(0xffffffffu, sz, off);
    }
    const int lane = threadIdx.x & 31, w = threadIdx.x >> 5;
    if (lane == 0) { sh[0][w] = sx; sh[1][w] = sy; sh[2][w] = sz; }
    __syncthreads();
    if (w == 0) {
        const int nw = blockDim.x >> 5;
        sx = (lane < nw) ? sh[0][lane] : 0.f;
        sy = (lane < nw) ? sh[1][lane] : 0.f;
        sz = (lane < nw) ? sh[2][lane] : 0.f;
        #pragma unroll
        for (int off = 16; off; off >>= 1) {
            sx += __shfl_down_sync(0xffffffffu, sx, off);
            sy += __shfl_down_sync(0xffffffffu, sy, off);
            sz += __shfl_down_sync(0xffffffffu, sz, off);
        }
        if (lane == 0) {
            g_mean[b][0] = sx / (float)NN;
            g_mean[b][1] = sy / (float)NN;
            g_mean[b][2] = sz / (float)NN;
        }
    }
}

// ---------------------------------------------------------------------------
// Per-batch max centered norm -> denominator (one block per batch)
// ---------------------------------------------------------------------------
__global__ void k_maxnorm(const float* __restrict__ coords) {
    const int b = blockIdx.x;
    const float* cb = coords + (size_t)b * NN * 3;
    const float mx = g_mean[b][0], my = g_mean[b][1], mz = g_mean[b][2];
    float m = 0.f;
    for (int n = threadIdx.x; n < NN; n += blockDim.x) {
        float dx = cb[n * 3 + 0] - mx;
        float dy = cb[n * 3 + 1] - my;
        float dz = cb[n * 3 + 2] - mz;
        float s = dx * dx + dy * dy + dz * dz;
        m = fmaxf(m, s);
    }
    __shared__ float sh[32];
    #pragma unroll
    for (int off = 16; off; off >>= 1)
        m = fmaxf(m, __shfl_down_sync(0xffffffffu, m, off));
    const int lane = threadIdx.x & 31, w = threadIdx.x >> 5;
    if (lane == 0) sh[w] = m;
    __syncthreads();
    if (w == 0) {
        const int nw = blockDim.x >> 5;
        m = (lane < nw) ? sh[lane] : 0.f;
        #pragma unroll
        for (int off = 16; off; off >>= 1)
            m = fmaxf(m, __shfl_down_sync(0xffffffffu, m, off));
        if (lane == 0)
            g_denom[b] = __fmaf_rn(2.f, sqrtf(m), EPSF);
    }
}

// ---------------------------------------------------------------------------
// Per-point: normalized coords (2nd output), voxel index, count atomic
// ---------------------------------------------------------------------------
__global__ void k_points(const float* __restrict__ coords,
                         float* __restrict__ out_nc, int write_nc) {
    const int t = blockIdx.x * blockDim.x + threadIdx.x;
    if (t >= BB * NN) return;
    const int b = t >> 15;  // / NN
    const float d = g_denom[b];
    const float mx = g_mean[b][0], my = g_mean[b][1], mz = g_mean[b][2];

    const float x = coords[(size_t)t * 3 + 0];
    const float y = coords[(size_t)t * 3 + 1];
    const float z = coords[(size_t)t * 3 + 2];

    // match reference arithmetic: (c - mean)/denom + 0.5, IEEE rn regardless of fast-math
    const float nx = __fadd_rn(__fdiv_rn(__fsub_rn(x, mx), d), 0.5f);
    const float ny = __fadd_rn(__fdiv_rn(__fsub_rn(y, my), d), 0.5f);
    const float nz = __fadd_rn(__fdiv_rn(__fsub_rn(z, mz), d), 0.5f);

    // jnp.round == round-half-even == __float2int_rn
    int vx = __float2int_rn(__fmul_rn(nx, (float)(RR - 1)));
    int vy = __float2int_rn(__fmul_rn(ny, (float)(RR - 1)));
    int vz = __float2int_rn(__fmul_rn(nz, (float)(RR - 1)));
    vx = min(max(vx, 0), RR - 1);
    vy = min(max(vy, 0), RR - 1);
    vz = min(max(vz, 0), RR - 1);

    const int idx = vx * (RR * RR) + vy * RR + vz;
    g_idx[t] = idx;
    atomicAdd(&g_cnt[b * R3 + idx], 1);

    if (write_nc) {
        out_nc[(size_t)t * 3 + 0] = nx;
        out_nc[(size_t)t * 3 + 1] = ny;
        out_nc[(size_t)t * 3 + 2] = nz;
    }
}

// ---------------------------------------------------------------------------
// Feature scatter: one thread per (point, float4-chunk). Coalesced loads,
// vector float4 atomics into [b][voxel][c] layout.
// ---------------------------------------------------------------------------
__global__ void k_scatter(const float* __restrict__ features) {
    const int t = blockIdx.x * blockDim.x + threadIdx.x;  // < B*N*16
    if (t >= BB * NN * (CC / 4)) return;
    const int p = t >> 4;       // point id
    const int k = t & 15;       // float4 chunk within 64 channels
    const int b = p >> 15;      // / NN
    const int idx = g_idx[p];

    const float4 f = reinterpret_cast<const float4*>(features)[t];
    float4* dst = reinterpret_cast<float4*>(
        &g_sums[((size_t)b * R3 + idx) * CC + k * 4]);
    atomicAdd(dst, f);
}

// ---------------------------------------------------------------------------
// Finalize: divide by max(count,1) and transpose [v][c] -> [c][v]
// ---------------------------------------------------------------------------
__global__ void k_final(float* __restrict__ out) {
    __shared__ float tile[32][33];
    __shared__ float icnt[32];
    const int b = blockIdx.z;
    const int v0 = blockIdx.x * 32;
    const int c0 = blockIdx.y * 32;

    // load [32 voxels][32 channels], coalesced over channels
    #pragma unroll
    for (int i = threadIdx.y; i < 32; i += 8) {
        tile[i][threadIdx.x] =
            g_sums[((size_t)b * R3 + v0 + i) * CC + c0 + threadIdx.x];
    }
    if (threadIdx.y == 0) {
        int c = g_cnt[b * R3 + v0 + threadIdx.x];
        icnt[threadIdx.x] = (float)max(c, 1);
    }
    __syncthreads();

    // write out[b][c][v], coalesced over voxels
    #pragma unroll
    for (int i = threadIdx.y; i < 32; i += 8) {
        const int c = c0 + i;
        out[((size_t)b * CC + c) * R3 + v0 + threadIdx.x] =
            __fdiv_rn(tile[threadIdx.x][i], icnt[threadIdx.x]);
    }
}

// ---------------------------------------------------------------------------
extern "C" void kernel_launch(void* const* d_in, const int* in_sizes, int n_in,
                              void* d_out, int out_size) {
    const float* features = (const float*)d_in[0];
    const float* coords   = (const float*)d_in[1];
    float* out = (float*)d_out;

    const size_t avg_elems = (size_t)BB * CC * R3;     // 33,554,432
    const size_t nc_elems  = (size_t)BB * NN * 3;      // 1,572,864
    const int write_nc = ((size_t)out_size >= avg_elems + nc_elems) ? 1 : 0;
    float* out_nc = out + avg_elems;

    k_zero<<<8192, 256>>>();
    k_mean<<<BB, 1024>>>(coords);
    k_maxnorm<<<BB, 1024>>>(coords);
    k_points<<<(BB * NN + 255) / 256, 256>>>(coords, out_nc, write_nc);
    k_scatter<<<(BB * NN * (CC / 4) + 255) / 256, 256>>>(features);
    {
        dim3 grid(R3 / 32, CC / 32, BB);
        dim3 block(32, 8);
        k_final<<<grid, block>>>(out);
    }
}

// round 2
// speedup vs baseline: 1.0665x; 1.0665x over previous
#include <cuda_runtime.h>
#include <cuda_bf16.h>

#define BB 16
#define NN 32768
#define CC 64
#define RR 32
#define R3 (RR*RR*RR)
#define EPSF 1e-6f
#define NPART 8      // partial-reduction blocks per batch

// Scratch (device globals — no allocation allowed)
__device__ int   g_cnt[BB * R3];       // points per voxel
__device__ int   g_start[BB * R3];     // exclusive-scan start (global slot)
__device__ int   g_cursor[BB * R3];    // running cursor for reorder
__device__ int   g_idx[BB * NN];       // voxel index per point
__device__ int   g_order[BB * NN];     // point ids grouped by voxel
__device__ float g_part[BB * NPART][3];// partial coord sums
__device__ float g_mean[BB][3];
__device__ int   g_maxsq[BB];          // max squared norm, float bits (>=0)

// ---------------------------------------------------------------------------
// Zero the small scratch (counts + max)
// ---------------------------------------------------------------------------
__global__ void k_zero() {
    const int i = blockIdx.x * blockDim.x + threadIdx.x;
    int4* c4 = reinterpret_cast<int4*>(g_cnt);
    const int tot4 = BB * R3 / 4;
    for (int j = i; j < tot4; j += gridDim.x * blockDim.x)
        c4[j] = make_int4(0, 0, 0, 0);
    if (i < BB) g_maxsq[i] = 0;
}

// ---------------------------------------------------------------------------
// Stage-1 mean: 8 blocks per batch, deterministic partials
// ---------------------------------------------------------------------------
__global__ void k_mean1(const float* __restrict__ coords) {
    const int bid = blockIdx.x;           // 0..BB*NPART-1
    const int b = bid / NPART;
    const int part = bid % NPART;
    const int per = NN / NPART;           // 4096 points
    const float* cb = coords + ((size_t)b * NN + (size_t)part * per) * 3;

    float sx = 0.f, sy = 0.f, sz = 0.f;
    for (int n = threadIdx.x; n < per; n += blockDim.x) {
        sx += cb[n * 3 + 0];
        sy += cb[n * 3 + 1];
        sz += cb[n * 3 + 2];
    }
    #pragma unroll
    for (int off = 16; off; off >>= 1) {
        sx += __shfl_down_sync(0xffffffffu, sx, off);
        sy += __shfl_down_sync(0xffffffffu, sy, off);
        sz += __shfl_down_sync(0xffffffffu, sz, off);
    }
    __shared__ float sh[3][8];
    const int lane = threadIdx.x & 31, w = threadIdx.x >> 5;
    if (lane == 0) { sh[0][w] = sx; sh[1][w] = sy; sh[2][w] = sz; }
    __syncthreads();
    if (threadIdx.x == 0) {
        float ax = 0.f, ay = 0.f, az = 0.f;
        const int nw = blockDim.x >> 5;
        for (int k = 0; k < nw; k++) { ax += sh[0][k]; ay += sh[1][k]; az += sh[2][k]; }
        g_part[bid][0] = ax; g_part[bid][1] = ay; g_part[bid][2] = az;
    }
}

// Stage-2 mean: fixed-order combine (deterministic)
__global__ void k_mean2() {
    const int t = threadIdx.x;            // 48 active
    if (t < BB * 3) {
        const int b = t / 3, c = t % 3;
        float s = 0.f;
        for (int p = 0; p < NPART; p++) s += g_part[b * NPART + p][c];
        g_mean[b][c] = s / (float)NN;
    }
}

// ---------------------------------------------------------------------------
// Max centered squared norm per batch (atomicMax on float bits, order-free)
// ---------------------------------------------------------------------------
__global__ void k_maxnorm(const float* __restrict__ coords) {
    const int bid = blockIdx.x;
    const int b = bid / NPART;
    const int part = bid % NPART;
    const int per = NN / NPART;
    const float* cb = coords + ((size_t)b * NN + (size_t)part * per) * 3;
    const float mx = g_mean[b][0], my = g_mean[b][1], mz = g_mean[b][2];

    float m = 0.f;
    for (int n = threadIdx.x; n < per; n += blockDim.x) {
        float dx = cb[n * 3 + 0] - mx;
        float dy = cb[n * 3 + 1] - my;
        float dz = cb[n * 3 + 2] - mz;
        m = fmaxf(m, dx * dx + dy * dy + dz * dz);
    }
    #pragma unroll
    for (int off = 16; off; off >>= 1)
        m = fmaxf(m, __shfl_down_sync(0xffffffffu, m, off));
    __shared__ float sh[8];
    const int lane = threadIdx.x & 31, w = threadIdx.x >> 5;
    if (lane == 0) sh[w] = m;
    __syncthreads();
    if (threadIdx.x == 0) {
        const int nw = blockDim.x >> 5;
        for (int k = 0; k < nw; k++) m = fmaxf(m, sh[k]);
        atomicMax(&g_maxsq[b], __float_as_int(m));  // m >= 0, int order == float order
    }
}

// ---------------------------------------------------------------------------
// Per-point: normalized coords output, voxel index, count histogram
// ---------------------------------------------------------------------------
__global__ void k_points(const float* __restrict__ coords,
                         float* __restrict__ out_nc, int write_nc) {
    const int t = blockIdx.x * blockDim.x + threadIdx.x;
    if (t >= BB * NN) return;
    const int b = t >> 15;  // / NN
    const float d = __fmaf_rn(2.f, __fsqrt_rn(__int_as_float(g_maxsq[b])), EPSF);
    const float mx = g_mean[b][0], my = g_mean[b][1], mz = g_mean[b][2];

    const float x = coords[(size_t)t * 3 + 0];
    const float y = coords[(size_t)t * 3 + 1];
    const float z = coords[(size_t)t * 3 + 2];

    const float nx = __fadd_rn(__fdiv_rn(__fsub_rn(x, mx), d), 0.5f);
    const float ny = __fadd_rn(__fdiv_rn(__fsub_rn(y, my), d), 0.5f);
    const float nz = __fadd_rn(__fdiv_rn(__fsub_rn(z, mz), d), 0.5f);

    int vx = __float2int_rn(__fmul_rn(nx, (float)(RR - 1)));
    int vy = __float2int_rn(__fmul_rn(ny, (float)(RR - 1)));
    int vz = __float2int_rn(__fmul_rn(nz, (float)(RR - 1)));
    vx = min(max(vx, 0), RR - 1);
    vy = min(max(vy, 0), RR - 1);
    vz = min(max(vz, 0), RR - 1);

    const int idx = vx * (RR * RR) + vy * RR + vz;
    g_idx[t] = idx;
    atomicAdd(&g_cnt[b * R3 + idx], 1);

    if (write_nc) {
        out_nc[(size_t)t * 3 + 0] = nx;
        out_nc[(size_t)t * 3 + 1] = ny;
        out_nc[(size_t)t * 3 + 2] = nz;
    }
}

// ---------------------------------------------------------------------------
// Per-batch exclusive scan of counts -> g_start / g_cursor
// 1 block of 1024 threads per batch, 32 counts per thread.
// ---------------------------------------------------------------------------
__global__ void k_scan() {
    const int b = blockIdx.x;
    const int PER = R3 / 1024;            // 32
    const int base = b * R3 + threadIdx.x * PER;

    int vals[32];
    int tot = 0;
    #pragma unroll
    for (int i = 0; i < PER; i++) { vals[i] = g_cnt[base + i]; tot += vals[i]; }

    // block-wide exclusive scan of per-thread totals
    const int lane = threadIdx.x & 31, w = threadIdx.x >> 5;
    int inc = tot;
    #pragma unroll
    for (int off = 1; off < 32; off <<= 1) {
        int v = __shfl_up_sync(0xffffffffu, inc, off);
        if (lane >= off) inc += v;
    }
    __shared__ int wsum[32];
    if (lane == 31) wsum[w] = inc;
    __syncthreads();
    if (w == 0) {
        int s = wsum[lane];
        int si = s;
        #pragma unroll
        for (int off = 1; off < 32; off <<= 1) {
            int v = __shfl_up_sync(0xffffffffu, si, off);
            if (lane >= off) si += v;
        }
        wsum[lane] = si - s;              // exclusive warp-offsets
    }
    __syncthreads();
    const int ex = wsum[w] + inc - tot;   // exclusive prefix of this thread

    int run = b * NN + ex;
    #pragma unroll
    for (int i = 0; i < PER; i++) {
        g_start[base + i]  = run;
        g_cursor[base + i] = run;
        run += vals[i];
    }
}

// ---------------------------------------------------------------------------
// Reorder: group point ids by voxel
// ---------------------------------------------------------------------------
__global__ void k_reorder() {
    const int t = blockIdx.x * blockDim.x + threadIdx.x;
    if (t >= BB * NN) return;
    const int b = t >> 15;
    const int slot = atomicAdd(&g_cursor[b * R3 + g_idx[t]], 1);
    g_order[slot] = t;
}

// ---------------------------------------------------------------------------
// Fused gather + mean + transpose. Block = (16 chunks, 32 voxels).
// ---------------------------------------------------------------------------
__global__ void k_gather(const float* __restrict__ features,
                         float* __restrict__ out) {
    const int b  = blockIdx.y;
    const int v0 = blockIdx.x * 32;
    const int tx = threadIdx.x;           // float4 chunk 0..15
    const int ty = threadIdx.y;           // local voxel 0..31
    const int seg = b * R3 + v0 + ty;

    const int start = g_start[seg];
    const int cnt   = g_cnt[seg];
    const float4* f4 = reinterpret_cast<const float4*>(features);

    float4 acc = make_float4(0.f, 0.f, 0.f, 0.f);
    for (int j = 0; j < cnt; j++) {
        const int p = g_order[start + j];
        const float4 f = f4[(size_t)p * (CC / 4) + tx];
        acc.x += f.x; acc.y += f.y; acc.z += f.z; acc.w += f.w;
    }
    const float inv = 1.0f / (float)max(cnt, 1);
    acc.x *= inv; acc.y *= inv; acc.z *= inv; acc.w *= inv;

    __shared__ float sh[CC][33];
    sh[tx * 4 + 0][ty] = acc.x;
    sh[tx * 4 + 1][ty] = acc.y;
    sh[tx * 4 + 2][ty] = acc.z;
    sh[tx * 4 + 3][ty] = acc.w;
    __syncthreads();

    // 512 threads write 64x32 floats: coalesced over voxels
    const int tid = ty * 16 + tx;
    const int lane = tid & 31;
    #pragma unroll
    for (int r = 0; r < 4; r++) {
        const int c = (tid >> 5) + r * 16;
        out[((size_t)b * CC + c) * R3 + v0 + lane] = sh[c][lane];
    }
}

// ---------------------------------------------------------------------------
extern "C" void kernel_launch(void* const* d_in, const int* in_sizes, int n_in,
                              void* d_out, int out_size) {
    const float* features = (const float*)d_in[0];
    const float* coords   = (const float*)d_in[1];
    float* out = (float*)d_out;

    const size_t avg_elems = (size_t)BB * CC * R3;
    const size_t nc_elems  = (size_t)BB * NN * 3;
    const int write_nc = ((size_t)out_size >= avg_elems + nc_elems) ? 1 : 0;
    float* out_nc = out + avg_elems;

    k_zero<<<512, 256>>>();
    k_mean1<<<BB * NPART, 256>>>(coords);
    k_mean2<<<1, 64>>>();
    k_maxnorm<<<BB * NPART, 256>>>(coords);
    k_points<<<(BB * NN + 255) / 256, 256>>>(coords, out_nc, write_nc);
    k_scan<<<BB, 1024>>>();
    k_reorder<<<(BB * NN + 255) / 256, 256>>>();
    {
        dim3 grid(R3 / 32, BB);
        dim3 block(16, 32);
        k_gather<<<grid, block>>>(features, out);
    }
}

// round 3
// speedup vs baseline: 1.1446x; 1.0732x over previous
#include <cuda_runtime.h>
#include <cuda_bf16.h>

#define BB 16
#define NN 32768
#define CC 64
#define RR 32
#define R3 (RR*RR*RR)
#define EPSF 1e-6f
#define NPART 32     // partial-reduction blocks per batch

// Scratch (device globals — zero-initialized at load; no allocation allowed)
__device__ int   g_cnt[BB * R3];        // points per voxel (re-zeroed by k_gather)
__device__ int   g_start[BB * R3];      // exclusive-scan start (global slot)
__device__ int   g_cursor[BB * R3];     // running cursor for reorder
__device__ int   g_idx[BB * NN];        // voxel index per point
__device__ int   g_order[BB * NN];      // point ids grouped by voxel
__device__ float g_part[BB * NPART][3]; // partial coord sums
__device__ int   g_maxsq[BB];           // max squared norm, float bits (>=0)

// Deterministic mean recompute from partials (same order everywhere)
__device__ __forceinline__ void load_mean(int b, float m[3]) {
    float ax = 0.f, ay = 0.f, az = 0.f;
    #pragma unroll 4
    for (int p = 0; p < NPART; p++) {
        ax += g_part[b * NPART + p][0];
        ay += g_part[b * NPART + p][1];
        az += g_part[b * NPART + p][2];
    }
    m[0] = ax / (float)NN; m[1] = ay / (float)NN; m[2] = az / (float)NN;
}

// ---------------------------------------------------------------------------
// Stage-1 mean: NPART blocks per batch; also resets g_maxsq for this replay
// ---------------------------------------------------------------------------
__global__ void k_mean1(const float* __restrict__ coords) {
    const int bid = blockIdx.x;           // 0..BB*NPART-1
    const int b = bid / NPART;
    const int part = bid % NPART;
    const int per = NN / NPART;           // 1024 points
    const float* cb = coords + ((size_t)b * NN + (size_t)part * per) * 3;

    if (part == 0 && threadIdx.x == 0) g_maxsq[b] = 0;

    float sx = 0.f, sy = 0.f, sz = 0.f;
    for (int n = threadIdx.x; n < per; n += blockDim.x) {
        sx += cb[n * 3 + 0];
        sy += cb[n * 3 + 1];
        sz += cb[n * 3 + 2];
    }
    #pragma unroll
    for (int off = 16; off; off >>= 1) {
        sx += __shfl_down_sync(0xffffffffu, sx, off);
        sy += __shfl_down_sync(0xffffffffu, sy, off);
        sz += __shfl_down_sync(0xffffffffu, sz, off);
    }
    __shared__ float sh[3][8];
    const int lane = threadIdx.x & 31, w = threadIdx.x >> 5;
    if (lane == 0) { sh[0][w] = sx; sh[1][w] = sy; sh[2][w] = sz; }
    __syncthreads();
    if (threadIdx.x == 0) {
        float ax = 0.f, ay = 0.f, az = 0.f;
        const int nw = blockDim.x >> 5;
        for (int k = 0; k < nw; k++) { ax += sh[0][k]; ay += sh[1][k]; az += sh[2][k]; }
        g_part[bid][0] = ax; g_part[bid][1] = ay; g_part[bid][2] = az;
    }
}

// ---------------------------------------------------------------------------
// Max centered squared norm per batch (atomicMax on float bits, order-free)
// ---------------------------------------------------------------------------
__global__ void k_maxnorm(const float* __restrict__ coords) {
    const int bid = blockIdx.x;
    const int b = bid / NPART;
    const int part = bid % NPART;
    const int per = NN / NPART;
    const float* cb = coords + ((size_t)b * NN + (size_t)part * per) * 3;

    __shared__ float smean[3];
    if (threadIdx.x < 3) {
        float m[3];
        load_mean(b, m);
        smean[threadIdx.x] = m[threadIdx.x];
    }
    __syncthreads();
    const float mx = smean[0], my = smean[1], mz = smean[2];

    float m = 0.f;
    for (int n = threadIdx.x; n < per; n += blockDim.x) {
        float dx = cb[n * 3 + 0] - mx;
        float dy = cb[n * 3 + 1] - my;
        float dz = cb[n * 3 + 2] - mz;
        m = fmaxf(m, dx * dx + dy * dy + dz * dz);
    }
    #pragma unroll
    for (int off = 16; off; off >>= 1)
        m = fmaxf(m, __shfl_down_sync(0xffffffffu, m, off));
    __shared__ float sh[8];
    const int lane = threadIdx.x & 31, w = threadIdx.x >> 5;
    if (lane == 0) sh[w] = m;
    __syncthreads();
    if (threadIdx.x == 0) {
        const int nw = blockDim.x >> 5;
        for (int k = 0; k < nw; k++) m = fmaxf(m, sh[k]);
        atomicMax(&g_maxsq[b], __float_as_int(m));  // m >= 0: int order == float order
    }
}

// ---------------------------------------------------------------------------
// Per-point: normalized coords output, voxel index, count histogram
// ---------------------------------------------------------------------------
__global__ void k_points(const float* __restrict__ coords,
                         float* __restrict__ out_nc, int write_nc) {
    const int t = blockIdx.x * blockDim.x + threadIdx.x;
    const int b = t >> 15;  // / NN

    __shared__ float smean[3];
    __shared__ float sden;
    if (threadIdx.x < 3) {
        float m[3];
        load_mean(b, m);
        smean[threadIdx.x] = m[threadIdx.x];
        if (threadIdx.x == 0)
            sden = __fmaf_rn(2.f, __fsqrt_rn(__int_as_float(g_maxsq[b])), EPSF);
    }
    __syncthreads();
    const float d = sden;
    const float mx = smean[0], my = smean[1], mz = smean[2];

    const float x = coords[(size_t)t * 3 + 0];
    const float y = coords[(size_t)t * 3 + 1];
    const float z = coords[(size_t)t * 3 + 2];

    const float nx = __fadd_rn(__fdiv_rn(__fsub_rn(x, mx), d), 0.5f);
    const float ny = __fadd_rn(__fdiv_rn(__fsub_rn(y, my), d), 0.5f);
    const float nz = __fadd_rn(__fdiv_rn(__fsub_rn(z, mz), d), 0.5f);

    int vx = __float2int_rn(__fmul_rn(nx, (float)(RR - 1)));
    int vy = __float2int_rn(__fmul_rn(ny, (float)(RR - 1)));
    int vz = __float2int_rn(__fmul_rn(nz, (float)(RR - 1)));
    vx = min(max(vx, 0), RR - 1);
    vy = min(max(vy, 0), RR - 1);
    vz = min(max(vz, 0), RR - 1);

    const int idx = vx * (RR * RR) + vy * RR + vz;
    g_idx[t] = idx;
    atomicAdd(&g_cnt[b * R3 + idx], 1);

    if (write_nc) {
        out_nc[(size_t)t * 3 + 0] = nx;
        out_nc[(size_t)t * 3 + 1] = ny;
        out_nc[(size_t)t * 3 + 2] = nz;
    }
}

// NOTE: one block per batch (threads are a power of two, NN fixed) so the
// launch config below must keep gridDim.x == BB and blockDim.x == 1024.
__global__ void k_scan() {
    const int b = blockIdx.x;
    const int PER = R3 / 1024;            // 32
    const int base = b * R3 + threadIdx.x * PER;

    int vals[32];
    int tot = 0;
    #pragma unroll
    for (int i = 0; i < PER; i++) { vals[i] = g_cnt[base + i]; tot += vals[i]; }

    const int lane = threadIdx.x & 31, w = threadIdx.x >> 5;
    int inc = tot;
    #pragma unroll
    for (int off = 1; off < 32; off <<= 1) {
        int v = __shfl_up_sync(0xffffffffu, inc, off);
        if (lane >= off) inc += v;
    }
    __shared__ int wsum[32];
    if (lane == 31) wsum[w] = inc;
    __syncthreads();
    if (w == 0) {
        int s = wsum[lane];
        int si = s;
        #pragma unroll
        for (int off = 1; off < 32; off <<= 1) {
            int v = __shfl_up_sync(0xffffffffu, si, off);
            if (lane >= off) si += v;
        }
        wsum[lane] = si - s;
    }
    __syncthreads();
    const int ex = wsum[w] + inc - tot;

    int run = b * NN + ex;
    #pragma unroll
    for (int i = 0; i < PER; i++) {
        g_start[base + i]  = run;
        g_cursor[base + i] = run;
        run += vals[i];
    }
}

// ---------------------------------------------------------------------------
// Reorder: group point ids by voxel
// ---------------------------------------------------------------------------
__global__ void k_reorder() {
    const int t = blockIdx.x * blockDim.x + threadIdx.x;
    const int b = t >> 15;
    const int slot = atomicAdd(&g_cursor[b * R3 + g_idx[t]], 1);
    g_order[slot] = t;
}

// ---------------------------------------------------------------------------
// Fused gather + mean + transpose. Block = (8 lanes, 32 voxels); each thread
// owns 2 float4 chunks. Inner loop unrolled x2 -> 4 independent loads/iter.
// Epilogue re-zeroes g_cnt for the next graph replay.
// ---------------------------------------------------------------------------
__global__ void k_gather(const float* __restrict__ features,
                         float* __restrict__ out) {
    const int b  = blockIdx.y;
    const int v0 = blockIdx.x * 32;
    const int tx = threadIdx.x;           // 0..7
    const int ty = threadIdx.y;           // 0..31
    const int seg = b * R3 + v0 + ty;

    const int start = g_start[seg];
    const int cnt   = g_cnt[seg];
    const float4* f4 = reinterpret_cast<const float4*>(features);

    float4 a0 = make_float4(0.f, 0.f, 0.f, 0.f);
    float4 a1 = make_float4(0.f, 0.f, 0.f, 0.f);

    int j = 0;
    for (; j + 2 <= cnt; j += 2) {
        const int p0 = g_order[start + j];
        const int p1 = g_order[start + j + 1];
        const float4 x0 = __ldcs(&f4[(size_t)p0 * (CC / 4) + tx]);
        const float4 y0 = __ldcs(&f4[(size_t)p0 * (CC / 4) + tx + 8]);
        const float4 x1 = __ldcs(&f4[(size_t)p1 * (CC / 4) + tx]);
        const float4 y1 = __ldcs(&f4[(size_t)p1 * (CC / 4) + tx + 8]);
        a0.x += x0.x + x1.x; a0.y += x0.y + x1.y;
        a0.z += x0.z + x1.z; a0.w += x0.w + x1.w;
        a1.x += y0.x + y1.x; a1.y += y0.y + y1.y;
        a1.z += y0.z + y1.z; a1.w += y0.w + y1.w;
    }
    if (j < cnt) {
        const int p0 = g_order[start + j];
        const float4 x0 = __ldcs(&f4[(size_t)p0 * (CC / 4) + tx]);
        const float4 y0 = __ldcs(&f4[(size_t)p0 * (CC / 4) + tx + 8]);
        a0.x += x0.x; a0.y += x0.y; a0.z += x0.z; a0.w += x0.w;
        a1.x += y0.x; a1.y += y0.y; a1.z += y0.z; a1.w += y0.w;
    }

    const float inv = 1.0f / (float)max(cnt, 1);
    a0.x *= inv; a0.y *= inv; a0.z *= inv; a0.w *= inv;
    a1.x *= inv; a1.y *= inv; a1.z *= inv; a1.w *= inv;

    __shared__ float sh[CC][33];
    sh[tx * 4 + 0][ty] = a0.x;
    sh[tx * 4 + 1][ty] = a0.y;
    sh[tx * 4 + 2][ty] = a0.z;
    sh[tx * 4 + 3][ty] = a0.w;
    sh[(tx + 8) * 4 + 0][ty] = a1.x;
    sh[(tx + 8) * 4 + 1][ty] = a1.y;
    sh[(tx + 8) * 4 + 2][ty] = a1.z;
    sh[(tx + 8) * 4 + 3][ty] = a1.w;
    __syncthreads();

    // 256 threads write 64x32 floats: coalesced over voxels, streaming store
    const int tid = ty * 8 + tx;
    const int lane = tid & 31;
    #pragma unroll
    for (int r = 0; r < 8; r++) {
        const int c = (tid >> 5) + r * 8;
        __stcs(&out[((size_t)b * CC + c) * R3 + v0 + lane], sh[c][lane]);
    }

    // reset counts for the next replay
    if (tid < 32) g_cnt[b * R3 + v0 + tid] = 0;
}

// ---------------------------------------------------------------------------
extern "C" void kernel_launch(void* const* d_in, const int* in_sizes, int n_in,
                              void* d_out, int out_size) {
    const float* features = (const float*)d_in[0];
    const float* coords   = (const float*)d_in[1];
    float* out = (float*)d_out;

    const size_t avg_elems = (size_t)BB * CC * R3;
    const size_t nc_elems  = (size_t)BB * NN * 3;
    const int write_nc = ((size_t)out_size >= avg_elems + nc_elems) ? 1 : 0;
    float* out_nc = out + avg_elems;

    k_mean1<<<BB * NPART, 256>>>(coords);
    k_maxnorm<<<BB * NPART, 256>>>(coords);
    k_points<<<BB * NN / 256, 256>>>(coords, out_nc, write_nc);
    k_scan<<<BB, 1024>>>();
    k_reorder<<<BB * NN / 256, 256>>>();
    {
        dim3 grid(R3 / 32, BB);
        dim3 block(8, 32);
        k_gather<<<grid, block>>>(features, out);
    }
}

// round 4
// speedup vs baseline: 1.6450x; 1.4371x over previous
#include <cuda_runtime.h>
#include <cuda_bf16.h>

#define BB 16
#define NN 32768
#define CC 64
#define RR 32
#define R3 (RR*RR*RR)
#define EPSF 1e-6f
#define NPART 32     // partial-reduction blocks per batch
#define SCAN_BLKS 32 // scan blocks per batch (each covers 1024 counts)

// Scratch (device globals — zero-initialized at load; no allocation allowed)
__device__ __align__(16) int g_cnt[BB * R3];    // points per voxel (re-zeroed by k_gather)
__device__ __align__(16) int g_cursor[BB * R3]; // reorder cursor (ends at start+cnt)
__device__ int   g_idx[BB * NN];        // voxel index per point
__device__ int   g_order[BB * NN];      // point ids grouped by voxel
__device__ float g_part[BB * NPART][3]; // partial coord sums
__device__ int   g_maxsq[BB];           // max squared norm, float bits (>=0)
__device__ int   g_bsum[BB * SCAN_BLKS];// per-scan-block count sums
__device__ int   g_boff[BB * SCAN_BLKS];// exclusive offsets (incl. batch base)

// Deterministic mean recompute from partials (same order everywhere)
__device__ __forceinline__ void load_mean(int b, float m[3]) {
    float ax = 0.f, ay = 0.f, az = 0.f;
    #pragma unroll 4
    for (int p = 0; p < NPART; p++) {
        ax += g_part[b * NPART + p][0];
        ay += g_part[b * NPART + p][1];
        az += g_part[b * NPART + p][2];
    }
    m[0] = ax / (float)NN; m[1] = ay / (float)NN; m[2] = az / (float)NN;
}

// ---------------------------------------------------------------------------
// Stage-1 mean: NPART blocks per batch; also resets g_maxsq for this replay
// ---------------------------------------------------------------------------
__global__ void k_mean1(const float* __restrict__ coords) {
    const int bid = blockIdx.x;           // 0..BB*NPART-1
    const int b = bid / NPART;
    const int part = bid % NPART;
    const int per = NN / NPART;           // 1024 points
    const float* cb = coords + ((size_t)b * NN + (size_t)part * per) * 3;

    if (part == 0 && threadIdx.x == 0) g_maxsq[b] = 0;

    float sx = 0.f, sy = 0.f, sz = 0.f;
    for (int n = threadIdx.x; n < per; n += blockDim.x) {
        sx += cb[n * 3 + 0];
        sy += cb[n * 3 + 1];
        sz += cb[n * 3 + 2];
    }
    #pragma unroll
    for (int off = 16; off; off >>= 1) {
        sx += __shfl_down_sync(0xffffffffu, sx, off);
        sy += __shfl_down_sync(0xffffffffu, sy, off);
        sz += __shfl_down_sync(0xffffffffu, sz, off);
    }
    __shared__ float sh[3][8];
    const int lane = threadIdx.x & 31, w = threadIdx.x >> 5;
    if (lane == 0) { sh[0][w] = sx; sh[1][w] = sy; sh[2][w] = sz; }
    __syncthreads();
    if (threadIdx.x == 0) {
        float ax = 0.f, ay = 0.f, az = 0.f;
        const int nw = blockDim.x >> 5;
        for (int k = 0; k < nw; k++) { ax += sh[0][k]; ay += sh[1][k]; az += sh[2][k]; }
        g_part[bid][0] = ax; g_part[bid][1] = ay; g_part[bid][2] = az;
    }
}

// ---------------------------------------------------------------------------
// Max centered squared norm per batch (atomicMax on float bits, order-free)
// ---------------------------------------------------------------------------
__global__ void k_maxnorm(const float* __restrict__ coords) {
    const int bid = blockIdx.x;
    const int b = bid / NPART;
    const int part = bid % NPART;
    const int per = NN / NPART;
    const float* cb = coords + ((size_t)b * NN + (size_t)part * per) * 3;

    __shared__ float smean[3];
    if (threadIdx.x < 3) {
        float m[3];
        load_mean(b, m);
        smean[threadIdx.x] = m[threadIdx.x];
    }
    __syncthreads();
    const float mx = smean[0], my = smean[1], mz = smean[2];

    float m = 0.f;
    for (int n = threadIdx.x; n < per; n += blockDim.x) {
        float dx = cb[n * 3 + 0] - mx;
        float dy = cb[n * 3 + 1] - my;
        float dz = cb[n * 3 + 2] - mz;
        m = fmaxf(m, dx * dx + dy * dy + dz * dz);
    }
    #pragma unroll
    for (int off = 16; off; off >>= 1)
        m = fmaxf(m, __shfl_down_sync(0xffffffffu, m, off));
    __shared__ float sh[8];
    const int lane = threadIdx.x & 31, w = threadIdx.x >> 5;
    if (lane == 0) sh[w] = m;
    __syncthreads();
    if (threadIdx.x == 0) {
        const int nw = blockDim.x >> 5;
        for (int k = 0; k < nw; k++) m = fmaxf(m, sh[k]);
        atomicMax(&g_maxsq[b], __float_as_int(m));  // m >= 0: int order == float order
    }
}

// ---------------------------------------------------------------------------
// Per-point: normalized coords output, voxel index, count histogram
// ---------------------------------------------------------------------------
__global__ void k_points(const float* __restrict__ coords,
                         float* __restrict__ out_nc, int write_nc) {
    const int t = blockIdx.x * blockDim.x + threadIdx.x;
    const int b = t >> 15;  // / NN

    __shared__ float smean[3];
    __shared__ float sden;
    if (threadIdx.x < 3) {
        float m[3];
        load_mean(b, m);
        smean[threadIdx.x] = m[threadIdx.x];
        if (threadIdx.x == 0)
            sden = __fmaf_rn(2.f, __fsqrt_rn(__int_as_float(g_maxsq[b])), EPSF);
    }
    __syncthreads();
    const float d = sden;
    const float mx = smean[0], my = smean[1], mz = smean[2];

    const float x = coords[(size_t)t * 3 + 0];
    const float y = coords[(size_t)t * 3 + 1];
    const float z = coords[(size_t)t * 3 + 2];

    const float nx = __fadd_rn(__fdiv_rn(__fsub_rn(x, mx), d), 0.5f);
    const float ny = __fadd_rn(__fdiv_rn(__fsub_rn(y, my), d), 0.5f);
    const float nz = __fadd_rn(__fdiv_rn(__fsub_rn(z, mz), d), 0.5f);

    int vx = __float2int_rn(__fmul_rn(nx, (float)(RR - 1)));
    int vy = __float2int_rn(__fmul_rn(ny, (float)(RR - 1)));
    int vz = __float2int_rn(__fmul_rn(nz, (float)(RR - 1)));
    vx = min(max(vx, 0), RR - 1);
    vy = min(max(vy, 0), RR - 1);
    vz = min(max(vz, 0), RR - 1);

    const int idx = vx * (RR * RR) + vy * RR + vz;
    g_idx[t] = idx;
    atomicAdd(&g_cnt[b * R3 + idx], 1);

    if (write_nc) {
        out_nc[(size_t)t * 3 + 0] = nx;
        out_nc[(size_t)t * 3 + 1] = ny;
        out_nc[(size_t)t * 3 + 2] = nz;
    }
}

// ---------------------------------------------------------------------------
// Hierarchical scan, stage 1: per-block sums of 1024 counts (coalesced int4)
// grid = BB*SCAN_BLKS (512), block = 256
// ---------------------------------------------------------------------------
__global__ void k_scan1() {
    const int4* c4 = reinterpret_cast<const int4*>(g_cnt);
    const int4 v = c4[blockIdx.x * 256 + threadIdx.x];
    int s = v.x + v.y + v.z + v.w;
    #pragma unroll
    for (int off = 16; off; off >>= 1)
        s += __shfl_down_sync(0xffffffffu, s, off);
    __shared__ int sh[8];
    const int lane = threadIdx.x & 31, w = threadIdx.x >> 5;
    if (lane == 0) sh[w] = s;
    __syncthreads();
    if (threadIdx.x == 0) {
        int t = 0;
        #pragma unroll
        for (int k = 0; k < 8; k++) t += sh[k];
        g_bsum[blockIdx.x] = t;
    }
}

// Stage 2: exclusive scan of the 32 block sums per batch (1 warp per batch)
__global__ void k_scan2() {
    const int w = threadIdx.x >> 5;       // batch
    const int lane = threadIdx.x & 31;    // scan-block within batch
    int v = g_bsum[w * SCAN_BLKS + lane];
    int inc = v;
    #pragma unroll
    for (int off = 1; off < 32; off <<= 1) {
        int u = __shfl_up_sync(0xffffffffu, inc, off);
        if (lane >= off) inc += u;
    }
    g_boff[w * SCAN_BLKS + lane] = w * NN + inc - v;
}

// Stage 3: block-local exclusive scan + offset -> g_cursor (coalesced int4)
__global__ void k_scan3() {
    const int4* c4 = reinterpret_cast<const int4*>(g_cnt);
    const int i4 = blockIdx.x * 256 + threadIdx.x;
    const int4 v = c4[i4];
    const int tsum = v.x + v.y + v.z + v.w;

    // block exclusive scan of per-thread sums
    const int lane = threadIdx.x & 31, w = threadIdx.x >> 5;
    int inc = tsum;
    #pragma unroll
    for (int off = 1; off < 32; off <<= 1) {
        int u = __shfl_up_sync(0xffffffffu, inc, off);
        if (lane >= off) inc += u;
    }
    __shared__ int wsum[8];
    if (lane == 31) wsum[w] = inc;
    __syncthreads();
    int woff = 0;
    #pragma unroll
    for (int k = 0; k < 8; k++) woff += (k < w) ? wsum[k] : 0;

    int base = g_boff[blockIdx.x] + woff + inc - tsum;
    int4 cur;
    cur.x = base;
    cur.y = base + v.x;
    cur.z = cur.y + v.y;
    cur.w = cur.z + v.z;
    reinterpret_cast<int4*>(g_cursor)[i4] = cur;
}

// ---------------------------------------------------------------------------
// Reorder: group point ids by voxel
// ---------------------------------------------------------------------------
__global__ void k_reorder() {
    const int t = blockIdx.x * blockDim.x + threadIdx.x;
    const int b = t >> 15;
    const int slot = atomicAdd(&g_cursor[b * R3 + g_idx[t]], 1);
    g_order[slot] = t;
}

// ---------------------------------------------------------------------------
// Fused gather + mean + transpose. Block = (8 lanes, 32 voxels); each thread
// owns 2 float4 chunks. start = cursor - cnt (cursor ended at start+cnt).
// Epilogue re-zeroes g_cnt for the next graph replay.
// ---------------------------------------------------------------------------
__global__ void k_gather(const float* __restrict__ features,
                         float* __restrict__ out) {
    const int b  = blockIdx.y;
    const int v0 = blockIdx.x * 32;
    const int tx = threadIdx.x;           // 0..7
    const int ty = threadIdx.y;           // 0..31
    const int seg = b * R3 + v0 + ty;

    const int cnt   = g_cnt[seg];
    const int start = g_cursor[seg] - cnt;
    const float4* f4 = reinterpret_cast<const float4*>(features);

    float4 a0 = make_float4(0.f, 0.f, 0.f, 0.f);
    float4 a1 = make_float4(0.f, 0.f, 0.f, 0.f);

    int j = 0;
    for (; j + 2 <= cnt; j += 2) {
        const int p0 = g_order[start + j];
        const int p1 = g_order[start + j + 1];
        const float4 x0 = __ldcs(&f4[(size_t)p0 * (CC / 4) + tx]);
        const float4 y0 = __ldcs(&f4[(size_t)p0 * (CC / 4) + tx + 8]);
        const float4 x1 = __ldcs(&f4[(size_t)p1 * (CC / 4) + tx]);
        const float4 y1 = __ldcs(&f4[(size_t)p1 * (CC / 4) + tx + 8]);
        a0.x += x0.x + x1.x; a0.y += x0.y + x1.y;
        a0.z += x0.z + x1.z; a0.w += x0.w + x1.w;
        a1.x += y0.x + y1.x; a1.y += y0.y + y1.y;
        a1.z += y0.z + y1.z; a1.w += y0.w + y1.w;
    }
    if (j < cnt) {
        const int p0 = g_order[start + j];
        const float4 x0 = __ldcs(&f4[(size_t)p0 * (CC / 4) + tx]);
        const float4 y0 = __ldcs(&f4[(size_t)p0 * (CC / 4) + tx + 8]);
        a0.x += x0.x; a0.y += x0.y; a0.z += x0.z; a0.w += x0.w;
        a1.x += y0.x; a1.y += y0.y; a1.z += y0.z; a1.w += y0.w;
    }

    const float inv = 1.0f / (float)max(cnt, 1);
    a0.x *= inv; a0.y *= inv; a0.z *= inv; a0.w *= inv;
    a1.x *= inv; a1.y *= inv; a1.z *= inv; a1.w *= inv;

    __shared__ float sh[CC][33];
    sh[tx * 4 + 0][ty] = a0.x;
    sh[tx * 4 + 1][ty] = a0.y;
    sh[tx * 4 + 2][ty] = a0.z;
    sh[tx * 4 + 3][ty] = a0.w;
    sh[(tx + 8) * 4 + 0][ty] = a1.x;
    sh[(tx + 8) * 4 + 1][ty] = a1.y;
    sh[(tx + 8) * 4 + 2][ty] = a1.z;
    sh[(tx + 8) * 4 + 3][ty] = a1.w;
    __syncthreads();

    // 256 threads write 64x32 floats: coalesced over voxels, streaming store
    const int tid = ty * 8 + tx;
    const int lane = tid & 31;
    #pragma unroll
    for (int r = 0; r < 8; r++) {
        const int c = (tid >> 5) + r * 8;
        __stcs(&out[((size_t)b * CC + c) * R3 + v0 + lane], sh[c][lane]);
    }

    // reset counts for the next replay
    if (tid < 32) g_cnt[b * R3 + v0 + tid] = 0;
}

// ---------------------------------------------------------------------------
extern "C" void kernel_launch(void* const* d_in, const int* in_sizes, int n_in,
                              void* d_out, int out_size) {
    const float* features = (const float*)d_in[0];
    const float* coords   = (const float*)d_in[1];
    float* out = (float*)d_out;

    const size_t avg_elems = (size_t)BB * CC * R3;
    const size_t nc_elems  = (size_t)BB * NN * 3;
    const int write_nc = ((size_t)out_size >= avg_elems + nc_elems) ? 1 : 0;
    float* out_nc = out + avg_elems;

    k_mean1<<<BB * NPART, 256>>>(coords);
    k_maxnorm<<<BB * NPART, 256>>>(coords);
    k_points<<<BB * NN / 256, 256>>>(coords, out_nc, write_nc);
    k_scan1<<<BB * SCAN_BLKS, 256>>>();
    k_scan2<<<1, BB * 32>>>();
    k_scan3<<<BB * SCAN_BLKS, 256>>>();
    k_reorder<<<BB * NN / 256, 256>>>();
    {
        dim3 grid(R3 / 32, BB);
        dim3 block(8, 32);
        k_gather<<<grid, block>>>(features, out);
    }
}